// round 1
// baseline (speedup 1.0000x reference)
#include <cuda_runtime.h>
#include <cuda_bf16.h>
#include <math.h>

// Problem constants
#define S_LEN 4096
#define HID   2048
#define NH    16
#define NKV   4
#define DH    128
#define BLK   64
#define NBLK  64      // S/BLK
#define MSK   32      // sketch dim
#define KTOP  8

// ---------------- scratch (device globals; no allocation allowed) ----------------
__device__ float g_q[S_LEN * NH * DH];        // [s][h*128+d], post-RoPE
__device__ float g_k[S_LEN * NKV * DH];
__device__ float g_v[S_LEN * NKV * DH];
__device__ float g_qbar[NH * NBLK * DH];
__device__ float g_kbar[NKV * NBLK * DH];
__device__ float g_Sq[NH * NBLK * MSK];
__device__ float g_Sk[NKV * NBLK * MSK];
__device__ int   g_idx[NH * NBLK * KTOP];
__device__ float g_attn[S_LEN * NH * DH];
__device__ float g_cos[S_LEN * (DH / 2)];
__device__ float g_sin[S_LEN * (DH / 2)];

// ---------------- SGEMM: C[M,N] = A[M,K] @ B[K,N], all row-major, dims % 128/8 == 0 ----------------
__global__ void __launch_bounds__(256) sgemm128(const float* __restrict__ A,
                                                const float* __restrict__ B,
                                                float* __restrict__ C,
                                                int M, int N, int K) {
    __shared__ float As[8][128];
    __shared__ float Bs[8][128];
    const int tid = threadIdx.x;
    const int bx = blockIdx.x;   // N tile
    const int by = blockIdx.y;   // M tile

    const int ty = tid >> 4;     // 0..15
    const int tx = tid & 15;     // 0..15

    const int aRow = tid >> 1;          // 0..127
    const int aCol = (tid & 1) * 4;     // 0 or 4
    const int bRow = tid >> 5;          // 0..7
    const int bCol = (tid & 31) * 4;    // 0..124

    const float* Ab = A + (size_t)by * 128 * K;
    const float* Bb = B + (size_t)bx * 128;

    float acc[8][8];
#pragma unroll
    for (int i = 0; i < 8; i++)
#pragma unroll
        for (int j = 0; j < 8; j++) acc[i][j] = 0.f;

    for (int k0 = 0; k0 < K; k0 += 8) {
        float4 a4 = *(const float4*)(Ab + (size_t)aRow * K + k0 + aCol);
        As[aCol + 0][aRow] = a4.x;
        As[aCol + 1][aRow] = a4.y;
        As[aCol + 2][aRow] = a4.z;
        As[aCol + 3][aRow] = a4.w;
        float4 b4 = *(const float4*)(Bb + (size_t)(k0 + bRow) * N + bCol);
        *(float4*)&Bs[bRow][bCol] = b4;
        __syncthreads();

#pragma unroll
        for (int kk = 0; kk < 8; kk++) {
            float4 a0 = *(float4*)&As[kk][ty * 8];
            float4 a1 = *(float4*)&As[kk][ty * 8 + 4];
            float4 b0 = *(float4*)&Bs[kk][tx * 8];
            float4 b1 = *(float4*)&Bs[kk][tx * 8 + 4];
            float a[8] = {a0.x, a0.y, a0.z, a0.w, a1.x, a1.y, a1.z, a1.w};
            float b[8] = {b0.x, b0.y, b0.z, b0.w, b1.x, b1.y, b1.z, b1.w};
#pragma unroll
            for (int i = 0; i < 8; i++)
#pragma unroll
                for (int j = 0; j < 8; j++) acc[i][j] += a[i] * b[j];
        }
        __syncthreads();
    }

    float* Cb = C + (size_t)(by * 128 + ty * 8) * N + bx * 128 + tx * 8;
#pragma unroll
    for (int i = 0; i < 8; i++) {
        float4 c0 = {acc[i][0], acc[i][1], acc[i][2], acc[i][3]};
        float4 c1 = {acc[i][4], acc[i][5], acc[i][6], acc[i][7]};
        *(float4*)(Cb + (size_t)i * N) = c0;
        *(float4*)(Cb + (size_t)i * N + 4) = c1;
    }
}

// ---------------- RoPE tables ----------------
__global__ void rope_tables(const int* __restrict__ pos_ids) {
    int idx = blockIdx.x * blockDim.x + threadIdx.x;
    if (idx >= S_LEN * 64) return;
    int i = idx & 63, s = idx >> 6;
    double inv = pow(10000.0, -(double)i / 64.0);
    float fr = (float)pos_ids[s] * (float)inv;
    g_cos[idx] = cosf(fr);
    g_sin[idx] = sinf(fr);
}

__global__ void rope_apply(float* __restrict__ X, int nheads) {
    int idx = blockIdx.x * blockDim.x + threadIdx.x;
    int total = S_LEN * nheads * 64;
    if (idx >= total) return;
    int i = idx & 63;
    int h = (idx >> 6) % nheads;
    int s = idx / (64 * nheads);
    float c = g_cos[s * 64 + i], sn = g_sin[s * 64 + i];
    float* p = X + (size_t)s * nheads * DH + h * DH + i;
    float x1 = p[0], x2 = p[64];
    p[0]  = x1 * c - x2 * sn;
    p[64] = x2 * c + x1 * sn;
}

// ---------------- block means (exploits linearity: mean then sketch) ----------------
__global__ void blockmean(const float* __restrict__ X, float* __restrict__ out, int nheads) {
    int h = blockIdx.x / NBLK, n = blockIdx.x % NBLK, d = threadIdx.x;  // 128 threads
    int ld = nheads * DH;
    const float* base = X + (size_t)(n * BLK) * ld + h * DH + d;
    float s = 0.f;
#pragma unroll 8
    for (int c = 0; c < BLK; ++c) s += base[(size_t)c * ld];
    out[(size_t)blockIdx.x * DH + d] = s * (1.f / 64.f);
}

// ---------------- sketch: S[row][m] = bar[row] . H[:,m] ----------------
__global__ void sketch(const float* __restrict__ bar, const float* __restrict__ H,
                       float* __restrict__ Sm) {
    int row = blockIdx.x, m = threadIdx.x;  // 32 threads
    float s = 0.f;
#pragma unroll 8
    for (int d = 0; d < DH; ++d) s += bar[(size_t)row * DH + d] * H[d * MSK + m];
    Sm[(size_t)row * MSK + m] = s;
}

// ---------------- block scores + top-8 selection ----------------
__global__ void bstopk() {
    __shared__ float val[64];
    __shared__ float v2[64];
    __shared__ int   i2[64];
    int h = blockIdx.x / NBLK, i = blockIdx.x % NBLK, j = threadIdx.x;  // 64 threads
    const float* sq = &g_Sq[(size_t)(h * NBLK + i) * MSK];
    const float* sk = &g_Sk[(size_t)((h >> 2) * NBLK + j) * MSK];
    float s = 0.f;
#pragma unroll
    for (int m = 0; m < MSK; ++m) s += sq[m] * sk[m];
    if (j > i) s = -1e9f;
    if (j == i) s = 1e9f;
    val[j] = s;
    for (int t = 0; t < KTOP; ++t) {
        __syncthreads();
        v2[j] = val[j];
        i2[j] = j;
        __syncthreads();
        for (int off = 32; off; off >>= 1) {
            if (j < off) {
                if (v2[j + off] > v2[j] ||
                    (v2[j + off] == v2[j] && i2[j + off] < i2[j])) {
                    v2[j] = v2[j + off];
                    i2[j] = i2[j + off];
                }
            }
            __syncthreads();
        }
        if (j == 0) {
            g_idx[(size_t)blockIdx.x * KTOP + t] = i2[0];
            val[i2[0]] = -3e38f;
        }
    }
}

// ---------------- sparse flash attention: one CTA per (h, qblock) ----------------
#define QLD 132     // padded row stride for Q/K/V in smem (mult of 4, conflict-light)
#define SLD 65
#define ATTN_SMEM ((3 * 64 * QLD + 64 * SLD) * 4)

__global__ void __launch_bounds__(256) attn_kernel() {
    extern __shared__ float sm[];
    float* Qs = sm;
    float* Ks = Qs + 64 * QLD;
    float* Vs = Ks + 64 * QLD;
    float* Ss = Vs + 64 * QLD;

    const int tid = threadIdx.x;
    const int h = blockIdx.x >> 6, n = blockIdx.x & 63, kv = h >> 2;

    // load Q block
    for (int i = tid; i < 64 * 32; i += 256) {
        int r = i >> 5, c4 = (i & 31) << 2;
        float4 v = *(const float4*)&g_q[(size_t)(n * 64 + r) * (NH * DH) + h * DH + c4];
        *(float4*)&Qs[r * QLD + c4] = v;
    }

    const int r_own = tid >> 2, g_own = tid & 3;
    float m_r = -1e30f, l_r = 0.f;
    float O[32];
#pragma unroll
    for (int i = 0; i < 32; i++) O[i] = 0.f;

    const int tq = (tid >> 4) << 2, tc = (tid & 15) << 2;

    for (int t = 0; t < KTOP; ++t) {
        __syncthreads();
        int b = g_idx[(size_t)(h * NBLK + n) * KTOP + t];
        for (int i = tid; i < 64 * 32; i += 256) {
            int r = i >> 5, c4 = (i & 31) << 2;
            size_t goff = (size_t)(b * 64 + r) * (NKV * DH) + kv * DH + c4;
            *(float4*)&Ks[r * QLD + c4] = *(const float4*)&g_k[goff];
            *(float4*)&Vs[r * QLD + c4] = *(const float4*)&g_v[goff];
        }
        __syncthreads();

        // scores: 4x4 per thread
        float acc[4][4];
#pragma unroll
        for (int i = 0; i < 4; i++)
#pragma unroll
            for (int j = 0; j < 4; j++) acc[i][j] = 0.f;

        for (int d4 = 0; d4 < DH; d4 += 4) {
            float4 A[4], Bv[4];
#pragma unroll
            for (int i = 0; i < 4; i++) A[i] = *(float4*)&Qs[(tq + i) * QLD + d4];
#pragma unroll
            for (int j = 0; j < 4; j++) Bv[j] = *(float4*)&Ks[(tc + j) * QLD + d4];
#pragma unroll
            for (int i = 0; i < 4; i++)
#pragma unroll
                for (int j = 0; j < 4; j++)
                    acc[i][j] += A[i].x * Bv[j].x + A[i].y * Bv[j].y +
                                 A[i].z * Bv[j].z + A[i].w * Bv[j].w;
        }
        const int qbase = n * 64, kbase = b * 64;
#pragma unroll
        for (int i = 0; i < 4; i++)
#pragma unroll
            for (int j = 0; j < 4; j++) {
                float s = acc[i][j] * 0.08838834764831843f;  // 1/sqrt(128)
                if (kbase + tc + j > qbase + tq + i) s = -1e9f;
                Ss[(tq + i) * SLD + tc + j] = s;
            }
        __syncthreads();

        // streaming softmax update (4 threads per query row, 32 d each)
        float bm = -1e30f;
        const float* srow = &Ss[r_own * SLD];
#pragma unroll
        for (int c = g_own * 16; c < g_own * 16 + 16; ++c) bm = fmaxf(bm, srow[c]);
        bm = fmaxf(bm, __shfl_xor_sync(0xffffffffu, bm, 1));
        bm = fmaxf(bm, __shfl_xor_sync(0xffffffffu, bm, 2));
        float mn = fmaxf(m_r, bm);
        float scale = expf(m_r - mn);
        l_r *= scale;
#pragma unroll
        for (int i = 0; i < 32; i++) O[i] *= scale;

        float lsum = 0.f;
        for (int c = 0; c < 64; ++c) {
            float p = expf(srow[c] - mn);
            lsum += p;
            const float* vrow = &Vs[c * QLD + g_own * 32];
#pragma unroll
            for (int dd = 0; dd < 32; dd += 4) {
                float4 vv = *(const float4*)&vrow[dd];
                O[dd + 0] += p * vv.x;
                O[dd + 1] += p * vv.y;
                O[dd + 2] += p * vv.z;
                O[dd + 3] += p * vv.w;
            }
        }
        l_r += lsum;
        m_r = mn;
    }

    float inv = 1.f / l_r;
    float* outp = &g_attn[(size_t)(n * 64 + r_own) * (NH * DH) + h * DH + g_own * 32];
#pragma unroll
    for (int dd = 0; dd < 32; dd += 4) {
        float4 o = {O[dd] * inv, O[dd + 1] * inv, O[dd + 2] * inv, O[dd + 3] * inv};
        *(float4*)&outp[dd] = o;
    }
}

// ---------------- launch ----------------
extern "C" void kernel_launch(void* const* d_in, const int* in_sizes, int n_in,
                              void* d_out, int out_size) {
    const float* hs  = (const float*)d_in[0];
    const int*   pos = (const int*)  d_in[1];
    const float* Wq  = (const float*)d_in[2];
    const float* Wk  = (const float*)d_in[3];
    const float* Wv  = (const float*)d_in[4];
    const float* Wo  = (const float*)d_in[5];
    const float* H   = (const float*)d_in[6];
    float* out = (float*)d_out;

    cudaFuncSetAttribute(attn_kernel, cudaFuncAttributeMaxDynamicSharedMemorySize, ATTN_SMEM);

    float *q, *k, *v, *qbar, *kbar, *Sq, *Sk, *attn;
    cudaGetSymbolAddress((void**)&q,    g_q);
    cudaGetSymbolAddress((void**)&k,    g_k);
    cudaGetSymbolAddress((void**)&v,    g_v);
    cudaGetSymbolAddress((void**)&qbar, g_qbar);
    cudaGetSymbolAddress((void**)&kbar, g_kbar);
    cudaGetSymbolAddress((void**)&Sq,   g_Sq);
    cudaGetSymbolAddress((void**)&Sk,   g_Sk);
    cudaGetSymbolAddress((void**)&attn, g_attn);

    // 1) QKV projections
    sgemm128<<<dim3(NH * DH / 128, S_LEN / 128), 256>>>(hs, Wq, q, S_LEN, NH * DH, HID);
    sgemm128<<<dim3(NKV * DH / 128, S_LEN / 128), 256>>>(hs, Wk, k, S_LEN, NKV * DH, HID);
    sgemm128<<<dim3(NKV * DH / 128, S_LEN / 128), 256>>>(hs, Wv, v, S_LEN, NKV * DH, HID);

    // 2) RoPE
    rope_tables<<<(S_LEN * 64 + 255) / 256, 256>>>(pos);
    rope_apply<<<(S_LEN * NH * 64 + 255) / 256, 256>>>(q, NH);
    rope_apply<<<(S_LEN * NKV * 64 + 255) / 256, 256>>>(k, NKV);

    // 3) block means + sketch
    blockmean<<<NH * NBLK, DH>>>(q, qbar, NH);
    blockmean<<<NKV * NBLK, DH>>>(k, kbar, NKV);
    sketch<<<NH * NBLK, MSK>>>(qbar, H, Sq);
    sketch<<<NKV * NBLK, MSK>>>(kbar, H, Sk);

    // 4) block scores + top-8
    bstopk<<<NH * NBLK, 64>>>();

    // 5) sparse attention
    attn_kernel<<<NH * NBLK, 256, ATTN_SMEM>>>();

    // 6) output projection
    sgemm128<<<dim3(HID / 128, S_LEN / 128), 256>>>(attn, Wo, out, S_LEN, HID, HID);
}

// round 3
// speedup vs baseline: 1.3053x; 1.3053x over previous
#include <cuda_runtime.h>
#include <cuda_bf16.h>
#include <mma.h>
#include <math.h>
#include <stdint.h>

using namespace nvcuda;

// Problem constants
#define S_LEN 4096
#define HID   2048
#define NH    16
#define NKV   4
#define DH    128
#define BLK   64
#define NBLK  64
#define MSK   32
#define KTOP  8

// ---------------- scratch (device globals; no allocation allowed) ----------------
__device__ float g_q[S_LEN * NH * DH];
__device__ float g_k[S_LEN * NKV * DH];
__device__ float g_v[S_LEN * NKV * DH];
__device__ float g_qbar[NH * NBLK * DH];
__device__ float g_kbar[NKV * NBLK * DH];
__device__ float g_Sq[NH * NBLK * MSK];
__device__ float g_Sk[NKV * NBLK * MSK];
__device__ int   g_idx[NH * NBLK * KTOP];
__device__ float g_attn[S_LEN * NH * DH];
__device__ float g_cos[S_LEN * (DH / 2)];
__device__ float g_sin[S_LEN * (DH / 2)];
__device__ float g_invf[64];

// bf16 split operands (weights kept in natural [K,N] layout — wmma row-major B)
__device__ __nv_bfloat16 g_Ahi[S_LEN * HID];
__device__ __nv_bfloat16 g_Alo[S_LEN * HID];
__device__ __nv_bfloat16 g_Phi[S_LEN * NH * DH];
__device__ __nv_bfloat16 g_Plo[S_LEN * NH * DH];
__device__ __nv_bfloat16 g_Wqhi[HID * NH * DH];
__device__ __nv_bfloat16 g_Wqlo[HID * NH * DH];
__device__ __nv_bfloat16 g_Wkhi[HID * NKV * DH];
__device__ __nv_bfloat16 g_Wklo[HID * NKV * DH];
__device__ __nv_bfloat16 g_Wvhi[HID * NKV * DH];
__device__ __nv_bfloat16 g_Wvlo[HID * NKV * DH];
__device__ __nv_bfloat16 g_Wohi[HID * NH * DH];
__device__ __nv_bfloat16 g_Wolo[HID * NH * DH];

// ---------------- bf16x3 wmma GEMM: C[M,N] = A[M,K] @ B[K,N] ----------------
// A row-major hi/lo bf16, B row-major hi/lo bf16, C fp32 row-major.
// CTA tile 128x128, 8 warps (4x2), warp tile 32x64, K-chunk 32.
#define ALD 40      // A smem row stride (elems), 128 rows x 32 cols
#define BLD 136     // B smem row stride (elems), 32 rows x 128 cols

__global__ void __launch_bounds__(256) wmma_gemm(const __nv_bfloat16* __restrict__ Ahi,
                                                 const __nv_bfloat16* __restrict__ Alo,
                                                 const __nv_bfloat16* __restrict__ Bhi,
                                                 const __nv_bfloat16* __restrict__ Blo,
                                                 float* __restrict__ C,
                                                 int M, int N, int K) {
    __shared__ __nv_bfloat16 Ash[128 * ALD];
    __shared__ __nv_bfloat16 Asl[128 * ALD];
    __shared__ __nv_bfloat16 Bsh[32 * BLD];
    __shared__ __nv_bfloat16 Bsl[32 * BLD];

    const int tid = threadIdx.x, wid = tid >> 5;
    const int wm = wid >> 1, wn = wid & 1;          // 4 x 2 warp grid
    const int tM = blockIdx.y, tN = blockIdx.x;

    wmma::fragment<wmma::accumulator, 16, 16, 16, float> acc[2][4];
#pragma unroll
    for (int i = 0; i < 2; i++)
#pragma unroll
        for (int j = 0; j < 4; j++) wmma::fill_fragment(acc[i][j], 0.f);

    const __nv_bfloat16* pAh = Ahi + (size_t)tM * 128 * K;
    const __nv_bfloat16* pAl = Alo + (size_t)tM * 128 * K;
    const __nv_bfloat16* pBh = Bhi + (size_t)tN * 128;
    const __nv_bfloat16* pBl = Blo + (size_t)tN * 128;

    for (int c0 = 0; c0 < K; c0 += 32) {
        __syncthreads();
        // A tiles: 128x32 bf16 = 512 16B-granules each (4 per row)
#pragma unroll
        for (int rep = 0; rep < 2; rep++) {
            int g = rep * 256 + tid;
            int row = g >> 2, gc = g & 3;
            size_t go = (size_t)row * K + c0 + gc * 8;
            *(uint4*)&Ash[row * ALD + gc * 8] = *(const uint4*)(pAh + go);
            *(uint4*)&Asl[row * ALD + gc * 8] = *(const uint4*)(pAl + go);
        }
        // B tiles: 32x128 bf16 = 512 granules each (16 per row)
#pragma unroll
        for (int rep = 0; rep < 2; rep++) {
            int g = rep * 256 + tid;
            int row = g >> 4, gc = g & 15;
            size_t go = (size_t)(c0 + row) * N + gc * 8;
            *(uint4*)&Bsh[row * BLD + gc * 8] = *(const uint4*)(pBh + go);
            *(uint4*)&Bsl[row * BLD + gc * 8] = *(const uint4*)(pBl + go);
        }
        __syncthreads();

#pragma unroll
        for (int kk = 0; kk < 32; kk += 16) {
            wmma::fragment<wmma::matrix_a, 16, 16, 16, __nv_bfloat16, wmma::row_major> ah[2], al[2];
            wmma::fragment<wmma::matrix_b, 16, 16, 16, __nv_bfloat16, wmma::row_major> bh[4], bl[4];
#pragma unroll
            for (int i = 0; i < 2; i++) {
                wmma::load_matrix_sync(ah[i], &Ash[(wm * 32 + i * 16) * ALD + kk], ALD);
                wmma::load_matrix_sync(al[i], &Asl[(wm * 32 + i * 16) * ALD + kk], ALD);
            }
#pragma unroll
            for (int j = 0; j < 4; j++) {
                wmma::load_matrix_sync(bh[j], &Bsh[kk * BLD + wn * 64 + j * 16], BLD);
                wmma::load_matrix_sync(bl[j], &Bsl[kk * BLD + wn * 64 + j * 16], BLD);
            }
#pragma unroll
            for (int i = 0; i < 2; i++)
#pragma unroll
                for (int j = 0; j < 4; j++) {
                    wmma::mma_sync(acc[i][j], ah[i], bh[j], acc[i][j]);
                    wmma::mma_sync(acc[i][j], ah[i], bl[j], acc[i][j]);
                    wmma::mma_sync(acc[i][j], al[i], bh[j], acc[i][j]);
                }
        }
    }

#pragma unroll
    for (int i = 0; i < 2; i++)
#pragma unroll
        for (int j = 0; j < 4; j++) {
            float* cp = C + (size_t)(tM * 128 + wm * 32 + i * 16) * N + tN * 128 + wn * 64 + j * 16;
            wmma::store_matrix_sync(cp, acc[i][j], N, wmma::mem_row_major);
        }
}

// ---------------- bf16 split converter ----------------
__global__ void split_f32(const float* __restrict__ X, __nv_bfloat16* __restrict__ hi,
                          __nv_bfloat16* __restrict__ lo, int n) {
    int i = blockIdx.x * blockDim.x + threadIdx.x;
    if (i >= n) return;
    float v = X[i];
    __nv_bfloat16 h = __float2bfloat16(v);
    hi[i] = h;
    lo[i] = __float2bfloat16(v - __bfloat162float(h));
}

// ---------------- RoPE ----------------
__global__ void invf_kernel() {
    int i = threadIdx.x;
    g_invf[i] = (float)pow(10000.0, -(double)i / 64.0);
}
__global__ void rope_tables(const int* __restrict__ pos_ids) {
    int idx = blockIdx.x * blockDim.x + threadIdx.x;
    if (idx >= S_LEN * 64) return;
    int i = idx & 63, s = idx >> 6;
    float fr = (float)pos_ids[s] * g_invf[i];
    g_cos[idx] = cosf(fr);
    g_sin[idx] = sinf(fr);
}
__global__ void rope_apply(float* __restrict__ X, int nheads) {
    int idx = blockIdx.x * blockDim.x + threadIdx.x;
    int total = S_LEN * nheads * 64;
    if (idx >= total) return;
    int i = idx & 63;
    int h = (idx >> 6) % nheads;
    int s = idx / (64 * nheads);
    float c = g_cos[s * 64 + i], sn = g_sin[s * 64 + i];
    float* p = X + (size_t)s * nheads * DH + h * DH + i;
    float x1 = p[0], x2 = p[64];
    p[0]  = x1 * c - x2 * sn;
    p[64] = x2 * c + x1 * sn;
}

// ---------------- block means ----------------
__global__ void blockmean(const float* __restrict__ X, float* __restrict__ out, int nheads) {
    int h = blockIdx.x / NBLK, n = blockIdx.x % NBLK, d = threadIdx.x;
    int ld = nheads * DH;
    const float* base = X + (size_t)(n * BLK) * ld + h * DH + d;
    float s = 0.f;
#pragma unroll 8
    for (int c = 0; c < BLK; ++c) s += base[(size_t)c * ld];
    out[(size_t)blockIdx.x * DH + d] = s * (1.f / 64.f);
}

// ---------------- sketch ----------------
__global__ void sketch(const float* __restrict__ bar, const float* __restrict__ H,
                       float* __restrict__ Sm) {
    int row = blockIdx.x, m = threadIdx.x;
    float s = 0.f;
#pragma unroll 8
    for (int d = 0; d < DH; ++d) s += bar[(size_t)row * DH + d] * H[d * MSK + m];
    Sm[(size_t)row * MSK + m] = s;
}

// ---------------- block scores + top-8 ----------------
__global__ void bstopk() {
    __shared__ float val[64];
    __shared__ float v2[64];
    __shared__ int   i2[64];
    int h = blockIdx.x / NBLK, i = blockIdx.x % NBLK, j = threadIdx.x;
    const float* sq = &g_Sq[(size_t)(h * NBLK + i) * MSK];
    const float* sk = &g_Sk[(size_t)((h >> 2) * NBLK + j) * MSK];
    float s = 0.f;
#pragma unroll
    for (int m = 0; m < MSK; ++m) s += sq[m] * sk[m];
    if (j > i) s = -1e9f;
    if (j == i) s = 1e9f;
    val[j] = s;
    for (int t = 0; t < KTOP; ++t) {
        __syncthreads();
        v2[j] = val[j];
        i2[j] = j;
        __syncthreads();
        for (int off = 32; off; off >>= 1) {
            if (j < off) {
                if (v2[j + off] > v2[j] ||
                    (v2[j + off] == v2[j] && i2[j + off] < i2[j])) {
                    v2[j] = v2[j + off];
                    i2[j] = i2[j + off];
                }
            }
            __syncthreads();
        }
        if (j == 0) {
            g_idx[(size_t)blockIdx.x * KTOP + t] = i2[0];
            val[i2[0]] = -3e38f;
        }
    }
}

// ---------------- sparse flash attention ----------------
#define QLD 132
#define SLD 65
#define ATTN_SMEM ((3 * 64 * QLD + 64 * SLD) * 4)

__global__ void __launch_bounds__(256) attn_kernel() {
    extern __shared__ float smf[];
    float* Qs = smf;
    float* Ks = Qs + 64 * QLD;
    float* Vs = Ks + 64 * QLD;
    float* Ss = Vs + 64 * QLD;

    const int tid = threadIdx.x;
    const int h = blockIdx.x >> 6, n = blockIdx.x & 63, kv = h >> 2;

    for (int i = tid; i < 64 * 32; i += 256) {
        int r = i >> 5, c4 = (i & 31) << 2;
        float4 v = *(const float4*)&g_q[(size_t)(n * 64 + r) * (NH * DH) + h * DH + c4];
        *(float4*)&Qs[r * QLD + c4] = v;
    }

    const int r_own = tid >> 2, g_own = tid & 3;
    float m_r = -1e30f, l_r = 0.f;
    float O[32];
#pragma unroll
    for (int i = 0; i < 32; i++) O[i] = 0.f;

    const int tq = (tid >> 4) << 2, tc = (tid & 15) << 2;

    for (int t = 0; t < KTOP; ++t) {
        __syncthreads();
        int b = g_idx[(size_t)(h * NBLK + n) * KTOP + t];
        for (int i = tid; i < 64 * 32; i += 256) {
            int r = i >> 5, c4 = (i & 31) << 2;
            size_t goff = (size_t)(b * 64 + r) * (NKV * DH) + kv * DH + c4;
            *(float4*)&Ks[r * QLD + c4] = *(const float4*)&g_k[goff];
            *(float4*)&Vs[r * QLD + c4] = *(const float4*)&g_v[goff];
        }
        __syncthreads();

        float acc[4][4];
#pragma unroll
        for (int i = 0; i < 4; i++)
#pragma unroll
            for (int j = 0; j < 4; j++) acc[i][j] = 0.f;

        for (int d4 = 0; d4 < DH; d4 += 4) {
            float4 A[4], Bv[4];
#pragma unroll
            for (int i = 0; i < 4; i++) A[i] = *(float4*)&Qs[(tq + i) * QLD + d4];
#pragma unroll
            for (int j = 0; j < 4; j++) Bv[j] = *(float4*)&Ks[(tc + j) * QLD + d4];
#pragma unroll
            for (int i = 0; i < 4; i++)
#pragma unroll
                for (int j = 0; j < 4; j++)
                    acc[i][j] += A[i].x * Bv[j].x + A[i].y * Bv[j].y +
                                 A[i].z * Bv[j].z + A[i].w * Bv[j].w;
        }
        const int qbase = n * 64, kbase = b * 64;
#pragma unroll
        for (int i = 0; i < 4; i++)
#pragma unroll
            for (int j = 0; j < 4; j++) {
                float s = acc[i][j] * 0.08838834764831843f;
                if (kbase + tc + j > qbase + tq + i) s = -1e9f;
                Ss[(tq + i) * SLD + tc + j] = s;
            }
        __syncthreads();

        float bm = -1e30f;
        const float* srow = &Ss[r_own * SLD];
#pragma unroll
        for (int c = g_own * 16; c < g_own * 16 + 16; ++c) bm = fmaxf(bm, srow[c]);
        bm = fmaxf(bm, __shfl_xor_sync(0xffffffffu, bm, 1));
        bm = fmaxf(bm, __shfl_xor_sync(0xffffffffu, bm, 2));
        float mn = fmaxf(m_r, bm);
        float scale = expf(m_r - mn);
        l_r *= scale;
#pragma unroll
        for (int i = 0; i < 32; i++) O[i] *= scale;

        float lsum = 0.f;
        for (int c = 0; c < 64; ++c) {
            float p = expf(srow[c] - mn);
            lsum += p;
            const float* vrow = &Vs[c * QLD + g_own * 32];
#pragma unroll
            for (int dd = 0; dd < 32; dd += 4) {
                float4 vv = *(const float4*)&vrow[dd];
                O[dd + 0] += p * vv.x;
                O[dd + 1] += p * vv.y;
                O[dd + 2] += p * vv.z;
                O[dd + 3] += p * vv.w;
            }
        }
        l_r += lsum;
        m_r = mn;
    }

    float inv = 1.f / l_r;
    float* outp = &g_attn[(size_t)(n * 64 + r_own) * (NH * DH) + h * DH + g_own * 32];
#pragma unroll
    for (int dd = 0; dd < 32; dd += 4) {
        float4 o = {O[dd] * inv, O[dd + 1] * inv, O[dd + 2] * inv, O[dd + 3] * inv};
        *(float4*)&outp[dd] = o;
    }
}

// ---------------- launch ----------------
extern "C" void kernel_launch(void* const* d_in, const int* in_sizes, int n_in,
                              void* d_out, int out_size) {
    const float* hs  = (const float*)d_in[0];
    const int*   pos = (const int*)  d_in[1];
    const float* Wq  = (const float*)d_in[2];
    const float* Wk  = (const float*)d_in[3];
    const float* Wv  = (const float*)d_in[4];
    const float* Wo  = (const float*)d_in[5];
    const float* H   = (const float*)d_in[6];
    float* out = (float*)d_out;

    cudaFuncSetAttribute(attn_kernel, cudaFuncAttributeMaxDynamicSharedMemorySize, ATTN_SMEM);

    float *q, *k, *v, *qbar, *kbar, *Sq, *Sk, *attn;
    __nv_bfloat16 *Ahi, *Alo, *Phi, *Plo;
    __nv_bfloat16 *Wqhi, *Wqlo, *Wkhi, *Wklo, *Wvhi, *Wvlo, *Wohi, *Wolo;
    cudaGetSymbolAddress((void**)&q,    g_q);
    cudaGetSymbolAddress((void**)&k,    g_k);
    cudaGetSymbolAddress((void**)&v,    g_v);
    cudaGetSymbolAddress((void**)&qbar, g_qbar);
    cudaGetSymbolAddress((void**)&kbar, g_kbar);
    cudaGetSymbolAddress((void**)&Sq,   g_Sq);
    cudaGetSymbolAddress((void**)&Sk,   g_Sk);
    cudaGetSymbolAddress((void**)&attn, g_attn);
    cudaGetSymbolAddress((void**)&Ahi,  g_Ahi);
    cudaGetSymbolAddress((void**)&Alo,  g_Alo);
    cudaGetSymbolAddress((void**)&Phi,  g_Phi);
    cudaGetSymbolAddress((void**)&Plo,  g_Plo);
    cudaGetSymbolAddress((void**)&Wqhi, g_Wqhi);
    cudaGetSymbolAddress((void**)&Wqlo, g_Wqlo);
    cudaGetSymbolAddress((void**)&Wkhi, g_Wkhi);
    cudaGetSymbolAddress((void**)&Wklo, g_Wklo);
    cudaGetSymbolAddress((void**)&Wvhi, g_Wvhi);
    cudaGetSymbolAddress((void**)&Wvlo, g_Wvlo);
    cudaGetSymbolAddress((void**)&Wohi, g_Wohi);
    cudaGetSymbolAddress((void**)&Wolo, g_Wolo);

    // converts
    invf_kernel<<<1, 64>>>();
    split_f32<<<(S_LEN * HID + 255) / 256, 256>>>(hs, Ahi, Alo, S_LEN * HID);
    split_f32<<<(HID * NH * DH + 255) / 256, 256>>>(Wq, Wqhi, Wqlo, HID * NH * DH);
    split_f32<<<(HID * NKV * DH + 255) / 256, 256>>>(Wk, Wkhi, Wklo, HID * NKV * DH);
    split_f32<<<(HID * NKV * DH + 255) / 256, 256>>>(Wv, Wvhi, Wvlo, HID * NKV * DH);

    // 1) QKV projections on tensor cores (wmma bf16x3)
    wmma_gemm<<<dim3((NH * DH) / 128, S_LEN / 128), 256>>>(Ahi, Alo, Wqhi, Wqlo, q, S_LEN, NH * DH, HID);
    wmma_gemm<<<dim3((NKV * DH) / 128, S_LEN / 128), 256>>>(Ahi, Alo, Wkhi, Wklo, k, S_LEN, NKV * DH, HID);
    wmma_gemm<<<dim3((NKV * DH) / 128, S_LEN / 128), 256>>>(Ahi, Alo, Wvhi, Wvlo, v, S_LEN, NKV * DH, HID);

    // 2) RoPE
    rope_tables<<<(S_LEN * 64 + 255) / 256, 256>>>(pos);
    rope_apply<<<(S_LEN * NH * 64 + 255) / 256, 256>>>(q, NH);
    rope_apply<<<(S_LEN * NKV * 64 + 255) / 256, 256>>>(k, NKV);

    // 3) block means + sketch
    blockmean<<<NH * NBLK, DH>>>(q, qbar, NH);
    blockmean<<<NKV * NBLK, DH>>>(k, kbar, NKV);
    sketch<<<NH * NBLK, MSK>>>(qbar, H, Sq);
    sketch<<<NKV * NBLK, MSK>>>(kbar, H, Sk);

    // 4) block scores + top-8
    bstopk<<<NH * NBLK, 64>>>();

    // 5) sparse attention
    attn_kernel<<<NH * NBLK, 256, ATTN_SMEM>>>();

    // 6) output projection
    split_f32<<<(S_LEN * NH * DH + 255) / 256, 256>>>(attn, Phi, Plo, S_LEN * NH * DH);
    split_f32<<<(HID * NH * DH + 255) / 256, 256>>>(Wo, Wohi, Wolo, HID * NH * DH);
    wmma_gemm<<<dim3(HID / 128, S_LEN / 128), 256>>>(Phi, Plo, Wohi, Wolo, out, S_LEN, HID, HID);
}